// round 8
// baseline (speedup 1.0000x reference)
#include <cuda_runtime.h>
#include <cuda_bf16.h>

// Problem constants
#define BB 16
#define NN 64
#define HH 256
#define WW 256
#define HWXY (HH * WW)                 // 65536
#define TOTAL_ELEMS (BB * NN * HWXY)   // 67,108,864 per real/imag tensor
#define TOTAL_PIX (BB * HWXY)          // 1,048,576 pixels

__host__ __device__ constexpr int bitrev6(int m) {
    int r = 0;
    for (int i = 0; i < 6; i++) { r = (r << 1) | (m & 1); m >>= 1; }
    return r;
}

// One thread computes the full 64-point complex DFT of one (b,h,w) pixel.
// OUT_MODE 0: d_out = interleaved complex (float2 per element), 2*TOTAL_ELEMS floats.
// OUT_MODE 1: d_out = real part only (float per element), TOTAL_ELEMS floats.
template <int OUT_MODE>
__global__ void __launch_bounds__(128)
fft64_kernel(const float* __restrict__ re,
             const float* __restrict__ im,
             float* __restrict__ out)
{
    // Twiddles W_64^k = exp(-2*pi*i*k/64) = (cos(pi k/32), -sin(pi k/32)).
    // Function-local constexpr + full unroll -> FFMA immediates, no memory traffic.
    constexpr float TWR[32] = {
         1.000000000f,  0.995184727f,  0.980785280f,  0.956940336f,
         0.923879533f,  0.881921264f,  0.831469612f,  0.773010453f,
         0.707106781f,  0.634393284f,  0.555570233f,  0.471396737f,
         0.382683432f,  0.290284677f,  0.195090322f,  0.098017140f,
         0.000000000f, -0.098017140f, -0.195090322f, -0.290284677f,
        -0.382683432f, -0.471396737f, -0.555570233f, -0.634393284f,
        -0.707106781f, -0.773010453f, -0.831469612f, -0.881921264f,
        -0.923879533f, -0.956940336f, -0.980785280f, -0.995184727f
    };
    constexpr float TWI[32] = {   // = -sin(pi k / 32)
        -0.000000000f, -0.098017140f, -0.195090322f, -0.290284677f,
        -0.382683432f, -0.471396737f, -0.555570233f, -0.634393284f,
        -0.707106781f, -0.773010453f, -0.831469612f, -0.881921264f,
        -0.923879533f, -0.956940336f, -0.980785280f, -0.995184727f,
        -1.000000000f, -0.995184727f, -0.980785280f, -0.956940336f,
        -0.923879533f, -0.881921264f, -0.831469612f, -0.773010453f,
        -0.707106781f, -0.634393284f, -0.555570233f, -0.471396737f,
        -0.382683432f, -0.290284677f, -0.195090322f, -0.098017140f
    };

    const unsigned p  = blockIdx.x * 128u + threadIdx.x;  // pixel id
    if (p >= (unsigned)TOTAL_PIX) return;
    const unsigned b  = p >> 16;          // / HWXY
    const unsigned hw = p & 0xFFFFu;      // % HWXY

    const size_t base = (size_t)b * NN * HWXY + hw;
    const float* rp = re + base;
    const float* ip = im + base;

    float2 x[64];
#pragma unroll
    for (int n = 0; n < 64; n++) {
        x[n].x = rp[(size_t)n * HWXY];
        x[n].y = ip[(size_t)n * HWXY];
    }

    // Fully-unrolled radix-2 DIF FFT, 6 stages. Outputs in bit-reversed order.
#pragma unroll
    for (int s = 0; s < 6; s++) {
        const int half  = 32 >> s;
        const int tstep = 1 << s;
#pragma unroll
        for (int b0 = 0; b0 < 64; b0 += 2 * half) {
#pragma unroll
            for (int j = 0; j < half; j++) {
                const float2 u = x[b0 + j];
                const float2 v = x[b0 + j + half];
                const float dx = u.x - v.x;
                const float dy = u.y - v.y;
                x[b0 + j].x = u.x + v.x;
                x[b0 + j].y = u.y + v.y;
                const float wr = TWR[j * tstep];
                const float wi = TWI[j * tstep];
                x[b0 + j + half].x = dx * wr - dy * wi;
                x[b0 + j + half].y = dx * wi + dy * wr;
            }
        }
    }

    if (OUT_MODE == 0) {
        // Interleaved complex64 (float2), [B, N, H, W].
        float2* op = (float2*)out + base;
#pragma unroll
        for (int m = 0; m < 64; m++) {
            const int n = bitrev6(m);     // compile-time constant
            op[(size_t)n * HWXY] = x[m];
        }
    } else {
        // Real part only, float32 [B, N, H, W].
        float* op = out + base;
#pragma unroll
        for (int m = 0; m < 64; m++) {
            const int n = bitrev6(m);
            op[(size_t)n * HWXY] = x[m].x;
        }
    }
}

extern "C" void kernel_launch(void* const* d_in, const int* in_sizes, int n_in,
                              void* d_out, int out_size)
{
    // Bind inputs BY SIZE: adc tensors have exactly B*N*H*W = 67,108,864
    // elements; the 128x128 DFT weight (16,384) is unused (compile-time twiddles).
    const float* re = nullptr;
    const float* im = nullptr;
    for (int i = 0; i < n_in; i++) {
        if (in_sizes[i] == TOTAL_ELEMS) {
            if (!re)      re = (const float*)d_in[i];
            else if (!im) im = (const float*)d_in[i];
        }
    }
    if (!im) {
        for (int i = 0; i < n_in; i++) {
            if (in_sizes[i] == 2 * TOTAL_ELEMS) {  // packed real+imag fallback
                re = (const float*)d_in[i];
                im = re + TOTAL_ELEMS;
            }
        }
    }
    if (!re || !im) return;

    const int block = 128;
    const int grid  = TOTAL_PIX / block;  // 8192

    // Dispatch on out_size — the harness has no complex dtype, so the complex64
    // reference output was lowered to float32 either as interleaved pairs
    // (out_size = 2*TOTAL_ELEMS) or real-part-only (out_size = TOTAL_ELEMS).
    // Writing per this contract keeps all stores in-bounds.
    if (out_size >= 2 * TOTAL_ELEMS) {
        fft64_kernel<0><<<grid, block>>>(re, im, (float*)d_out);
    } else {
        fft64_kernel<1><<<grid, block>>>(re, im, (float*)d_out);
    }
}